// round 5
// baseline (speedup 1.0000x reference)
#include <cuda_runtime.h>
#include <cstdint>

#define N_NODES 100000
#define N_EDGES 1600000
#define IN_F   48
#define EDGE_F 32
#define HID_F  128
#define OUT_F  64

typedef unsigned long long ull;

#define SCAN_NB 391   // ceil(N_NODES/256)

// ---------------- scratch (device globals; allocation-free, .bss zero) ----------------
__device__ float4 g_h[N_NODES * 24];     // [N,96]  = [nfeat | mean-neigh0]
__device__ float4 g_hn1[N_NODES * 24];   // [N,96]  mean of h[src] per dst
__device__ float4 g_h1[N_NODES * 32];    // [N,128]
__device__ float4 g_y[N_NODES * 16];     // [N,64]  = h1 @ W2n
__device__ float4 g_hn2y[N_NODES * 16];  // [N,64]  mean of y[src] per dst
__device__ float  g_m[(size_t)N_EDGES * 48];  // per-edge messages, CSR order
__device__ unsigned g_cnt[N_NODES];      // in-degree (re-zeroed each run)
__device__ unsigned g_off[N_NODES + 1];  // CSR offsets
__device__ unsigned g_cur[N_NODES];      // scatter cursors
__device__ unsigned g_stat[512];         // lookback status (re-zeroed each run)
__device__ int g_ps[N_EDGES];            // src grouped by dst (CSR order)
__device__ int g_pos[N_EDGES];           // edge -> CSR position

// packed weights: element = (W[2kp][c], W[2kp+1][c]) as f32x2 in a u64
__device__ ull g_Wep[16 * 48];
__device__ ull g_W1p[96 * 128];
__device__ ull g_W2sp[64 * 64];
__device__ ull g_W2np[64 * 64];

// ---------------- helpers ----------------
__device__ __forceinline__ ull ffma2(ull a, ull b, ull c) {
    ull d;
    asm("fma.rn.f32x2 %0, %1, %2, %3;" : "=l"(d) : "l"(a), "l"(b), "l"(c));
    return d;
}
__device__ __forceinline__ ull f2u(float x, float y) {
    ull r;
    asm("mov.b64 %0, {%1,%2};" : "=l"(r) : "f"(x), "f"(y));
    return r;
}
__device__ __forceinline__ float2 u2f(ull v) {
    float2 r;
    asm("mov.b64 {%0,%1}, %2;" : "=f"(r.x), "=f"(r.y) : "l"(v));
    return r;
}
__device__ __forceinline__ void red_u32(unsigned* p, unsigned v) {
    asm volatile("red.global.add.u32 [%0], %1;" :: "l"(p), "r"(v) : "memory");
}

// ---------------- launch 0: weight prepack + degree histogram ----------------
__global__ void k_histprep(const int* __restrict__ dst, const float* __restrict__ We,
                           const float* __restrict__ W1s, const float* __restrict__ W1n,
                           const float* __restrict__ W2s, const float* __restrict__ W2n) {
    const int T0 = 16 * 48;
    const int T1 = T0 + 96 * 128;
    const int T2 = T1 + 64 * 64;
    const int T3 = T2 + 64 * 64;
    const int tid = blockIdx.x * blockDim.x + threadIdx.x;
    const int stride = gridDim.x * blockDim.x;
    for (int i = tid; i < T3; i += stride) {
        if (i < T0) {
            int kp = i / 48, c = i % 48;
            g_Wep[i] = f2u(We[(2 * kp) * 48 + c], We[(2 * kp + 1) * 48 + c]);
        } else if (i < T1) {
            int j = i - T0, kp = j / 128, c = j % 128;
            const float* W = (kp < 48) ? W1s : W1n;
            int k0 = (kp < 48) ? 2 * kp : 2 * (kp - 48);
            g_W1p[j] = f2u(W[k0 * 128 + c], W[(k0 + 1) * 128 + c]);
        } else if (i < T2) {
            int j = i - T1, kp = j / 64, c = j % 64;
            g_W2sp[j] = f2u(W2s[(2 * kp) * 64 + c], W2s[(2 * kp + 1) * 64 + c]);
        } else {
            int j = i - T2, kp = j / 64, c = j % 64;
            g_W2np[j] = f2u(W2n[(2 * kp) * 64 + c], W2n[(2 * kp + 1) * 64 + c]);
        }
    }
    for (int e = tid; e < N_EDGES; e += stride) red_u32(&g_cnt[dst[e]], 1u);
}

// ---------------- launch 1: single-kernel exclusive scan (decoupled lookback) ----------------
__global__ __launch_bounds__(256) void k_scan() {
    __shared__ unsigned sh[256];
    __shared__ unsigned s_excl;
    const int b = blockIdx.x, t = threadIdx.x;
    const int i = b * 256 + t;
    unsigned v = (i < N_NODES) ? g_cnt[i] : 0u;
    sh[t] = v;
    __syncthreads();
#pragma unroll
    for (int ofs = 1; ofs < 256; ofs <<= 1) {
        unsigned x = (t >= ofs) ? sh[t - ofs] : 0u;
        __syncthreads();
        sh[t] += x;
        __syncthreads();
    }
    const unsigned incl = sh[t];
    const unsigned T = sh[255];
    if (t == 0) {
        if (b > 0) atomicExch(&g_stat[b], 0x40000000u | T);  // AGG
        unsigned excl = 0;
        if (b > 0) {
            int p = b - 1;
            while (true) {
                unsigned s;
                do { s = *(volatile unsigned*)&g_stat[p]; } while (s < 0x40000000u);
                excl += s & 0x3FFFFFFFu;
                if (s >= 0x80000000u) break;  // PREFIX
                p--;
            }
        }
        atomicExch(&g_stat[b], 0x80000000u | (excl + T));
        s_excl = excl;
    }
    __syncthreads();
    if (i < N_NODES) {
        unsigned o = s_excl + incl - v;
        g_off[i] = o;
        g_cur[i] = o;
        g_cnt[i] = 0u;  // re-zero for next launch
    }
    if (i == 0) g_off[N_NODES] = N_EDGES;
}

// ---------------- launch 2: scatter (build g_ps CSR + inverse perm g_pos) ----------------
__global__ void k_scatter(const int* __restrict__ src, const int* __restrict__ dst) {
    const int tid = blockIdx.x * blockDim.x + threadIdx.x;
    if (tid < 512) g_stat[tid] = 0u;
    const int stride = gridDim.x * blockDim.x;
    for (int e = tid; e < N_EDGES; e += stride) {
        int d = dst[e];
        unsigned pos = atomicAdd(&g_cur[d], 1u);
        g_ps[pos] = src[e];
        g_pos[e] = (int)pos;
    }
}

// ---------------- launch 3: edge-parallel MLP, m -> CSR position ----------------
// m[pos[e]] = relu(efeat[e]@We + be) * nfeat[src[e]]   (48 floats)
__global__ __launch_bounds__(256) void k_edgeM(
    const float* __restrict__ efeat, const int* __restrict__ src,
    const float* __restrict__ nfeat, const float* __restrict__ be) {
    const int lane = threadIdx.x & 31;
    const int wl = threadIdx.x >> 5;
    const int w = blockIdx.x * 8 + wl;
    const int base = w * 8;  // 8 edges per warp; N_EDGES = 25000*64 exactly

    ull wp0[16], wp1[16];
#pragma unroll
    for (int kp = 0; kp < 16; kp++) wp0[kp] = g_Wep[kp * 48 + lane];
#pragma unroll
    for (int kp = 0; kp < 16; kp++)
        wp1[kp] = (lane < 16) ? g_Wep[kp * 48 + 32 + lane] : 0ull;
    const float bia0 = be[lane];
    const float bia1 = (lane < 16) ? be[32 + lane] : 0.0f;

    __shared__ __align__(16) float se[8][8][32];

#pragma unroll
    for (int j = 0; j < 8; j++)
        se[wl][j][lane] = efeat[(size_t)(base + j) * 32 + lane];

    int s_ = 0, p_ = 0;
    if (lane < 8) {
        s_ = src[base + lane];
        p_ = g_pos[base + lane];
    }
    __syncwarp();

    // prefetch nfeat gathers for all 8 edges (front-batched MLP)
    int ss[8];
#pragma unroll
    for (int j = 0; j < 8; j++) ss[j] = __shfl_sync(0xffffffffu, s_, j);
    float nfa[8], nfb[8];
#pragma unroll
    for (int j = 0; j < 8; j++) nfa[j] = nfeat[ss[j] * 48 + lane];
#pragma unroll
    for (int j = 0; j < 8; j++)
        nfb[j] = (lane < 16) ? nfeat[ss[j] * 48 + 32 + lane] : 0.0f;

#pragma unroll
    for (int j = 0; j < 8; j++) {
        int p = __shfl_sync(0xffffffffu, p_, j);
        ull a0 = 0, a1 = 0, a2 = 0, a3 = 0;
        ull b0 = 0, b1 = 0, b2 = 0, b3 = 0;
#pragma unroll
        for (int kp = 0; kp < 16; kp += 4) {
            ull x0 = *(const ull*)&se[wl][j][2 * kp];
            ull x1 = *(const ull*)&se[wl][j][2 * kp + 2];
            ull x2 = *(const ull*)&se[wl][j][2 * kp + 4];
            ull x3 = *(const ull*)&se[wl][j][2 * kp + 6];
            a0 = ffma2(x0, wp0[kp], a0);
            b0 = ffma2(x0, wp1[kp], b0);
            a1 = ffma2(x1, wp0[kp + 1], a1);
            b1 = ffma2(x1, wp1[kp + 1], b1);
            a2 = ffma2(x2, wp0[kp + 2], a2);
            b2 = ffma2(x2, wp1[kp + 2], b2);
            a3 = ffma2(x3, wp0[kp + 3], a3);
            b3 = ffma2(x3, wp1[kp + 3], b3);
        }
        float2 pa0 = u2f(a0), pa1 = u2f(a1), pa2 = u2f(a2), pa3 = u2f(a3);
        float r0 = ((pa0.x + pa0.y) + (pa1.x + pa1.y)) +
                   ((pa2.x + pa2.y) + (pa3.x + pa3.y));
        r0 = fmaxf(r0 + bia0, 0.0f) * nfa[j];
        float* mrow = g_m + (size_t)p * 48;
        mrow[lane] = r0;
        if (lane < 16) {
            float2 pb0 = u2f(b0), pb1 = u2f(b1), pb2 = u2f(b2), pb3 = u2f(b3);
            float r1 = ((pb0.x + pb0.y) + (pb1.x + pb1.y)) +
                       ((pb2.x + pb2.y) + (pb3.x + pb3.y));
            r1 = fmaxf(r1 + bia1, 0.0f) * nfb[j];
            mrow[32 + lane] = r1;
        }
    }
}

// ---------------- launch 4: h[d] = [nfeat[d] | mean contiguous m rows] ----------------
__global__ __launch_bounds__(256) void k_meanM(const float* __restrict__ nfeat) {
    const int lane = threadIdx.x & 31;
    const int d = blockIdx.x * 8 + (threadIdx.x >> 5);
    if (d >= N_NODES) return;
    const unsigned beg = g_off[d];
    const unsigned end = g_off[d + 1];
    const unsigned deg = end - beg;
    float a0 = 0.f, a1 = 0.f;
    unsigned i = beg;
    for (; i + 4 <= end; i += 4) {
        const float* r = g_m + (size_t)i * 48;
        float x0 = r[lane], x1 = r[48 + lane], x2 = r[96 + lane], x3 = r[144 + lane];
        a0 += (x0 + x1) + (x2 + x3);
        if (lane < 16) {
            float y0 = r[32 + lane], y1 = r[80 + lane];
            float y2 = r[128 + lane], y3 = r[176 + lane];
            a1 += (y0 + y1) + (y2 + y3);
        }
    }
    for (; i < end; i++) {
        const float* r = g_m + (size_t)i * 48;
        a0 += r[lane];
        if (lane < 16) a1 += r[32 + lane];
    }
    float iv = __fdividef(1.0f, fmaxf((float)deg, 1.0f));
    float* hrow = (float*)g_h + (size_t)d * 96;
    hrow[lane] = nfeat[d * 48 + lane];
    hrow[48 + lane] = a0 * iv;
    if (lane < 16) {
        hrow[32 + lane] = nfeat[d * 48 + 32 + lane];
        hrow[80 + lane] = a1 * iv;
    }
}

// ---------------- launch 5: hn1[d] = mean(h[src]) (96f, warp/node, unroll 4) ----------------
__global__ __launch_bounds__(256) void k_dstB() {
    const int lane = threadIdx.x & 31;
    const int d = blockIdx.x * 8 + (threadIdx.x >> 5);
    if (d >= N_NODES) return;
    const unsigned beg = g_off[d];
    const unsigned end = g_off[d + 1];
    const unsigned deg = end - beg;
    const float* hf = (const float*)g_h;
    float a0 = 0.f, a1 = 0.f, a2 = 0.f;
    unsigned i = beg;
    for (; i + 4 <= end; i += 4) {
        int s0 = g_ps[i], s1 = g_ps[i + 1], s2 = g_ps[i + 2], s3 = g_ps[i + 3];
        const float* r0 = hf + (size_t)s0 * 96;
        const float* r1 = hf + (size_t)s1 * 96;
        const float* r2 = hf + (size_t)s2 * 96;
        const float* r3 = hf + (size_t)s3 * 96;
        float x00 = r0[lane], x01 = r0[32 + lane], x02 = r0[64 + lane];
        float x10 = r1[lane], x11 = r1[32 + lane], x12 = r1[64 + lane];
        float x20 = r2[lane], x21 = r2[32 + lane], x22 = r2[64 + lane];
        float x30 = r3[lane], x31 = r3[32 + lane], x32 = r3[64 + lane];
        a0 += (x00 + x10) + (x20 + x30);
        a1 += (x01 + x11) + (x21 + x31);
        a2 += (x02 + x12) + (x22 + x32);
    }
    for (; i < end; i++) {
        const float* r0 = hf + (size_t)g_ps[i] * 96;
        a0 += r0[lane];
        a1 += r0[32 + lane];
        a2 += r0[64 + lane];
    }
    float iv = __fdividef(1.0f, fmaxf((float)deg, 1.0f));
    float* o = (float*)g_hn1 + (size_t)d * 96;
    o[lane] = a0 * iv;
    o[32 + lane] = a1 * iv;
    o[64 + lane] = a2 * iv;
}

// ---------------- launch 6: GEMM1 + fused y-projection ----------------
__global__ __launch_bounds__(128) void k_gemm1y(const float* __restrict__ b1) {
    __shared__ __align__(16) float As[32][192];
    __shared__ __align__(16) float Hs[32][128];
    const int tid = threadIdx.x;
    const int node0 = blockIdx.x * 32;
    for (int i = tid; i < 32 * 48; i += 128) {
        int n = i / 48, kq = i % 48;
        int node = node0 + n;
        float4 v = (kq < 24) ? g_h[node * 24 + kq] : g_hn1[node * 24 + (kq - 24)];
        ((float4*)As[n])[kq] = v;
    }
    __syncthreads();

    const int lane = tid & 31;
    const int nb = (tid >> 5) * 8;
    const int c0 = lane * 4;
    {
        ull acc[8][4];
#pragma unroll
        for (int n = 0; n < 8; n++)
#pragma unroll
            for (int j = 0; j < 4; j++) acc[n][j] = 0ull;

        for (int kq = 0; kq < 48; kq++) {
            const int kpA = 2 * kq, kpB = 2 * kq + 1;
            ulonglong2 wA0 = *(const ulonglong2*)&g_W1p[kpA * 128 + c0];
            ulonglong2 wA1 = *(const ulonglong2*)&g_W1p[kpA * 128 + c0 + 2];
            ulonglong2 wB0 = *(const ulonglong2*)&g_W1p[kpB * 128 + c0];
            ulonglong2 wB1 = *(const ulonglong2*)&g_W1p[kpB * 128 + c0 + 2];
#pragma unroll
            for (int n = 0; n < 8; n++) {
                ulonglong2 a = *(const ulonglong2*)&As[nb + n][4 * kq];
                acc[n][0] = ffma2(a.x, wA0.x, acc[n][0]);
                acc[n][1] = ffma2(a.x, wA0.y, acc[n][1]);
                acc[n][2] = ffma2(a.x, wA1.x, acc[n][2]);
                acc[n][3] = ffma2(a.x, wA1.y, acc[n][3]);
                acc[n][0] = ffma2(a.y, wB0.x, acc[n][0]);
                acc[n][1] = ffma2(a.y, wB0.y, acc[n][1]);
                acc[n][2] = ffma2(a.y, wB1.x, acc[n][2]);
                acc[n][3] = ffma2(a.y, wB1.y, acc[n][3]);
            }
        }

        float4 bb = *(const float4*)&b1[c0];
#pragma unroll
        for (int n = 0; n < 8; n++) {
            float2 p0 = u2f(acc[n][0]), p1 = u2f(acc[n][1]);
            float2 p2 = u2f(acc[n][2]), p3 = u2f(acc[n][3]);
            float4 r;
            r.x = fmaxf(p0.x + p0.y + bb.x, 0.0f);
            r.y = fmaxf(p1.x + p1.y + bb.y, 0.0f);
            r.z = fmaxf(p2.x + p2.y + bb.z, 0.0f);
            r.w = fmaxf(p3.x + p3.y + bb.w, 0.0f);
            g_h1[(node0 + nb + n) * 32 + lane] = r;
            ((float4*)Hs[nb + n])[lane] = r;
        }
    }
    __syncthreads();

    // y phase: 4 nodes per half-warp, 16 col-groups
    const int cg = lane & 15;
    const int c1 = cg * 4;
    const int nb2 = (tid >> 5) * 8 + (lane >> 4) * 4;
    ull acc[4][4];
#pragma unroll
    for (int n = 0; n < 4; n++)
#pragma unroll
        for (int j = 0; j < 4; j++) acc[n][j] = 0ull;

    for (int kq = 0; kq < 32; kq++) {
        const int kpA = 2 * kq, kpB = 2 * kq + 1;
        ulonglong2 wA0 = *(const ulonglong2*)&g_W2np[kpA * 64 + c1];
        ulonglong2 wA1 = *(const ulonglong2*)&g_W2np[kpA * 64 + c1 + 2];
        ulonglong2 wB0 = *(const ulonglong2*)&g_W2np[kpB * 64 + c1];
        ulonglong2 wB1 = *(const ulonglong2*)&g_W2np[kpB * 64 + c1 + 2];
#pragma unroll
        for (int n = 0; n < 4; n++) {
            ulonglong2 a = *(const ulonglong2*)&Hs[nb2 + n][4 * kq];
            acc[n][0] = ffma2(a.x, wA0.x, acc[n][0]);
            acc[n][1] = ffma2(a.x, wA0.y, acc[n][1]);
            acc[n][2] = ffma2(a.x, wA1.x, acc[n][2]);
            acc[n][3] = ffma2(a.x, wA1.y, acc[n][3]);
            acc[n][0] = ffma2(a.y, wB0.x, acc[n][0]);
            acc[n][1] = ffma2(a.y, wB0.y, acc[n][1]);
            acc[n][2] = ffma2(a.y, wB1.x, acc[n][2]);
            acc[n][3] = ffma2(a.y, wB1.y, acc[n][3]);
        }
    }
#pragma unroll
    for (int n = 0; n < 4; n++) {
        float2 p0 = u2f(acc[n][0]), p1 = u2f(acc[n][1]);
        float2 p2 = u2f(acc[n][2]), p3 = u2f(acc[n][3]);
        float4 r;
        r.x = p0.x + p0.y;
        r.y = p1.x + p1.y;
        r.z = p2.x + p2.y;
        r.w = p3.x + p3.y;
        g_y[(node0 + nb2 + n) * 16 + cg] = r;
    }
}

// ---------------- launch 7: hn2y[d] = mean(y[src]) (64f, warp/node, unroll 4) ----------------
__global__ __launch_bounds__(256) void k_dstC() {
    const int lane = threadIdx.x & 31;
    const int d = blockIdx.x * 8 + (threadIdx.x >> 5);
    if (d >= N_NODES) return;
    const unsigned beg = g_off[d];
    const unsigned end = g_off[d + 1];
    const unsigned deg = end - beg;
    const float* yf = (const float*)g_y;
    float a0 = 0.f, a1 = 0.f;
    unsigned i = beg;
    for (; i + 4 <= end; i += 4) {
        int s0 = g_ps[i], s1 = g_ps[i + 1], s2 = g_ps[i + 2], s3 = g_ps[i + 3];
        float2 x0 = *(const float2*)&yf[(size_t)s0 * 64 + 2 * lane];
        float2 x1 = *(const float2*)&yf[(size_t)s1 * 64 + 2 * lane];
        float2 x2 = *(const float2*)&yf[(size_t)s2 * 64 + 2 * lane];
        float2 x3 = *(const float2*)&yf[(size_t)s3 * 64 + 2 * lane];
        a0 += (x0.x + x1.x) + (x2.x + x3.x);
        a1 += (x0.y + x1.y) + (x2.y + x3.y);
    }
    for (; i < end; i++) {
        float2 x = *(const float2*)&yf[(size_t)g_ps[i] * 64 + 2 * lane];
        a0 += x.x;
        a1 += x.y;
    }
    float iv = __fdividef(1.0f, fmaxf((float)deg, 1.0f));
    float2* o = (float2*)((float*)g_hn2y + (size_t)d * 64);
    o[lane] = make_float2(a0 * iv, a1 * iv);
}

// ---------------- launch 8: out = h1@W2s + b2 + hn2y ----------------
__global__ __launch_bounds__(64) void k_gemm2s(const float* __restrict__ b2,
                                               float* __restrict__ out) {
    __shared__ __align__(16) float As[32][128];
    const int tid = threadIdx.x;
    const int node0 = blockIdx.x * 32;
    for (int i = tid; i < 32 * 32; i += 64) {
        int n = i / 32, kq = i % 32;
        ((float4*)As[n])[kq] = g_h1[(node0 + n) * 32 + kq];
    }
    __syncthreads();

    const int lane = tid & 31;
    const int cg = lane & 15;
    const int c0 = cg * 4;
    const int nb = (tid >> 5) * 16 + (lane >> 4) * 8;
    ull acc[8][4];
#pragma unroll
    for (int n = 0; n < 8; n++)
#pragma unroll
        for (int j = 0; j < 4; j++) acc[n][j] = 0ull;

    for (int kq = 0; kq < 32; kq++) {
        const int kpA = 2 * kq, kpB = 2 * kq + 1;
        ulonglong2 wA0 = *(const ulonglong2*)&g_W2sp[kpA * 64 + c0];
        ulonglong2 wA1 = *(const ulonglong2*)&g_W2sp[kpA * 64 + c0 + 2];
        ulonglong2 wB0 = *(const ulonglong2*)&g_W2sp[kpB * 64 + c0];
        ulonglong2 wB1 = *(const ulonglong2*)&g_W2sp[kpB * 64 + c0 + 2];
#pragma unroll
        for (int n = 0; n < 8; n++) {
            ulonglong2 a = *(const ulonglong2*)&As[nb + n][4 * kq];
            acc[n][0] = ffma2(a.x, wA0.x, acc[n][0]);
            acc[n][1] = ffma2(a.x, wA0.y, acc[n][1]);
            acc[n][2] = ffma2(a.x, wA1.x, acc[n][2]);
            acc[n][3] = ffma2(a.x, wA1.y, acc[n][3]);
            acc[n][0] = ffma2(a.y, wB0.x, acc[n][0]);
            acc[n][1] = ffma2(a.y, wB0.y, acc[n][1]);
            acc[n][2] = ffma2(a.y, wB1.x, acc[n][2]);
            acc[n][3] = ffma2(a.y, wB1.y, acc[n][3]);
        }
    }

    float4 bb = *(const float4*)&b2[c0];
    float4* out4 = (float4*)out;
#pragma unroll
    for (int n = 0; n < 8; n++) {
        int node = node0 + nb + n;
        float4 hz = g_hn2y[node * 16 + cg];
        float2 p0 = u2f(acc[n][0]), p1 = u2f(acc[n][1]);
        float2 p2 = u2f(acc[n][2]), p3 = u2f(acc[n][3]);
        float4 r;
        r.x = p0.x + p0.y + bb.x + hz.x;
        r.y = p1.x + p1.y + bb.y + hz.y;
        r.z = p2.x + p2.y + bb.z + hz.z;
        r.w = p3.x + p3.y + bb.w + hz.w;
        out4[node * 16 + cg] = r;
    }
}

// ---------------- launch ----------------
extern "C" void kernel_launch(void* const* d_in, const int* in_sizes, int n_in,
                              void* d_out, int out_size) {
    const float* nfeat = (const float*)d_in[0];
    const float* efeat = (const float*)d_in[1];
    const int*   src   = (const int*)d_in[2];
    const int*   dst   = (const int*)d_in[3];
    const float* We    = (const float*)d_in[4];
    const float* be    = (const float*)d_in[5];
    const float* W1s   = (const float*)d_in[6];
    const float* W1n   = (const float*)d_in[7];
    const float* b1    = (const float*)d_in[8];
    const float* W2s   = (const float*)d_in[9];
    const float* W2n   = (const float*)d_in[10];
    const float* b2    = (const float*)d_in[11];
    float* out = (float*)d_out;

    k_histprep<<<1184, 256>>>(dst, We, W1s, W1n, W2s, W2n);   // 0
    k_scan<<<SCAN_NB, 256>>>();                               // 1
    k_scatter<<<1184, 256>>>(src, dst);                       // 2
    k_edgeM<<<N_EDGES / 64, 256>>>(efeat, src, nfeat, be);    // 3  <- profiled
    k_meanM<<<(N_NODES + 7) / 8, 256>>>(nfeat);               // 4
    k_dstB<<<(N_NODES + 7) / 8, 256>>>();                     // 5
    k_gemm1y<<<N_NODES / 32, 128>>>(b1);                      // 6
    k_dstC<<<(N_NODES + 7) / 8, 256>>>();                     // 7
    k_gemm2s<<<N_NODES / 32, 64>>>(b2, out);                  // 8
}

// round 6
// speedup vs baseline: 1.2392x; 1.2392x over previous
#include <cuda_runtime.h>
#include <cstdint>

#define N_NODES 100000
#define N_EDGES 1600000
#define IN_F   48
#define EDGE_F 32
#define HID_F  128
#define OUT_F  64

typedef unsigned long long ull;

#define SCAN_NB 391   // ceil(N_NODES/256)
#define TILE_E 128

// ---------------- scratch (device globals; allocation-free, .bss zero) ----------------
__device__ float4 g_h[N_NODES * 24];     // [N,96]  = [nfeat | mean-neigh0]
__device__ float4 g_hn1[N_NODES * 24];   // [N,96]  mean of h[src] per dst
__device__ float4 g_h1[N_NODES * 32];    // [N,128]
__device__ float4 g_y[N_NODES * 16];     // [N,64]  = h1 @ W2n
__device__ float4 g_hn2y[N_NODES * 16];  // [N,64]  mean of y[src] per dst
__device__ float  g_m[(size_t)N_EDGES * 48];  // per-edge relu(e), CSR order
__device__ unsigned g_cnt[N_NODES];      // in-degree (re-zeroed each run)
__device__ unsigned g_off[N_NODES + 1];  // CSR offsets
__device__ unsigned g_cur[N_NODES];      // scatter cursors
__device__ unsigned g_stat[512];         // lookback status (re-zeroed each run)
__device__ int g_ps[N_EDGES];            // src grouped by dst (CSR order)
__device__ int g_pos[N_EDGES];           // edge -> CSR position

// packed weights
__device__ ull g_Wecp[32 * 24];          // We col-pair packed: [k][cp]=(W[k][2cp],W[k][2cp+1])
__device__ ull g_W1p[96 * 128];          // [W1s;W1n] k-pair packed
__device__ ull g_W2sp[64 * 64];          // W2s k-pair packed
__device__ ull g_W2np[64 * 64];          // W2n k-pair packed

// ---------------- helpers ----------------
__device__ __forceinline__ ull ffma2(ull a, ull b, ull c) {
    ull d;
    asm("fma.rn.f32x2 %0, %1, %2, %3;" : "=l"(d) : "l"(a), "l"(b), "l"(c));
    return d;
}
__device__ __forceinline__ ull f2u(float x, float y) {
    ull r;
    asm("mov.b64 %0, {%1,%2};" : "=l"(r) : "f"(x), "f"(y));
    return r;
}
__device__ __forceinline__ float2 u2f(ull v) {
    float2 r;
    asm("mov.b64 {%0,%1}, %2;" : "=f"(r.x), "=f"(r.y) : "l"(v));
    return r;
}
__device__ __forceinline__ void red_u32(unsigned* p, unsigned v) {
    asm volatile("red.global.add.u32 [%0], %1;" :: "l"(p), "r"(v) : "memory");
}

// ---------------- launch 0: weight prepack + degree histogram ----------------
__global__ void k_histprep(const int* __restrict__ dst, const float* __restrict__ We,
                           const float* __restrict__ W1s, const float* __restrict__ W1n,
                           const float* __restrict__ W2s, const float* __restrict__ W2n) {
    const int T0 = 32 * 24;
    const int T1 = T0 + 96 * 128;
    const int T2 = T1 + 64 * 64;
    const int T3 = T2 + 64 * 64;
    const int tid = blockIdx.x * blockDim.x + threadIdx.x;
    const int stride = gridDim.x * blockDim.x;
    for (int i = tid; i < T3; i += stride) {
        if (i < T0) {
            int k = i / 24, cp = i % 24;
            g_Wecp[i] = f2u(We[k * 48 + 2 * cp], We[k * 48 + 2 * cp + 1]);
        } else if (i < T1) {
            int j = i - T0, kp = j / 128, c = j % 128;
            const float* W = (kp < 48) ? W1s : W1n;
            int k0 = (kp < 48) ? 2 * kp : 2 * (kp - 48);
            g_W1p[j] = f2u(W[k0 * 128 + c], W[(k0 + 1) * 128 + c]);
        } else if (i < T2) {
            int j = i - T1, kp = j / 64, c = j % 64;
            g_W2sp[j] = f2u(W2s[(2 * kp) * 64 + c], W2s[(2 * kp + 1) * 64 + c]);
        } else {
            int j = i - T2, kp = j / 64, c = j % 64;
            g_W2np[j] = f2u(W2n[(2 * kp) * 64 + c], W2n[(2 * kp + 1) * 64 + c]);
        }
    }
    for (int e = tid; e < N_EDGES; e += stride) red_u32(&g_cnt[dst[e]], 1u);
}

// ---------------- launch 1: single-kernel exclusive scan (decoupled lookback) ----------------
__global__ __launch_bounds__(256) void k_scan() {
    __shared__ unsigned sh[256];
    __shared__ unsigned s_excl;
    const int b = blockIdx.x, t = threadIdx.x;
    const int i = b * 256 + t;
    unsigned v = (i < N_NODES) ? g_cnt[i] : 0u;
    sh[t] = v;
    __syncthreads();
#pragma unroll
    for (int ofs = 1; ofs < 256; ofs <<= 1) {
        unsigned x = (t >= ofs) ? sh[t - ofs] : 0u;
        __syncthreads();
        sh[t] += x;
        __syncthreads();
    }
    const unsigned incl = sh[t];
    const unsigned T = sh[255];
    if (t == 0) {
        if (b > 0) atomicExch(&g_stat[b], 0x40000000u | T);  // AGG
        unsigned excl = 0;
        if (b > 0) {
            int p = b - 1;
            while (true) {
                unsigned s;
                do { s = *(volatile unsigned*)&g_stat[p]; } while (s < 0x40000000u);
                excl += s & 0x3FFFFFFFu;
                if (s >= 0x80000000u) break;  // PREFIX
                p--;
            }
        }
        atomicExch(&g_stat[b], 0x80000000u | (excl + T));
        s_excl = excl;
    }
    __syncthreads();
    if (i < N_NODES) {
        unsigned o = s_excl + incl - v;
        g_off[i] = o;
        g_cur[i] = o;
        g_cnt[i] = 0u;  // re-zero for next launch
    }
    if (i == 0) g_off[N_NODES] = N_EDGES;
}

// ---------------- launch 2: scatter (build g_ps CSR + inverse perm g_pos) ----------------
__global__ void k_scatter(const int* __restrict__ src, const int* __restrict__ dst) {
    const int tid = blockIdx.x * blockDim.x + threadIdx.x;
    if (tid < 512) g_stat[tid] = 0u;
    const int stride = gridDim.x * blockDim.x;
    for (int e = tid; e < N_EDGES; e += stride) {
        int d = dst[e];
        unsigned pos = atomicAdd(&g_cur[d], 1u);
        g_ps[pos] = src[e];
        g_pos[e] = (int)pos;
    }
}

// ---------------- launch 3: tiled GEMM: g_m[pos[e]] = relu(efeat[e]@We + be) ----------------
// block 256 thr; tile 128 edges x 48 cols; warp <-> 6-col group; lane <-> 4 edges.
__global__ __launch_bounds__(256) void k_edgeGEMM(const float* __restrict__ efeat,
                                                  const float* __restrict__ be) {
    __shared__ __align__(16) float At[32][132];  // [k][edge], stride 132 floats
    __shared__ ull Ws[32][24];                   // col-pair-packed We
    const int tid = threadIdx.x;
    const int e0 = blockIdx.x * TILE_E;

    for (int i = tid; i < 32 * 24; i += 256) ((ull*)Ws)[0 * 0 + i] = g_Wecp[i];

    // load + transpose efeat tile (coalesced float4 reads, scalar STS)
    const float4* ef4 = (const float4*)efeat + (size_t)e0 * 8;
#pragma unroll
    for (int i = 0; i < 4; i++) {
        int idx = tid + 256 * i;
        int e = idx >> 3, q = idx & 7;
        float4 v = ef4[e * 8 + q];
        At[4 * q + 0][e] = v.x;
        At[4 * q + 1][e] = v.y;
        At[4 * q + 2][e] = v.z;
        At[4 * q + 3][e] = v.w;
    }
    __syncthreads();

    const int lane = tid & 31;
    const int cg = tid >> 5;  // 0..7
    ull acc[4][3];
#pragma unroll
    for (int j = 0; j < 4; j++)
#pragma unroll
        for (int c = 0; c < 3; c++) acc[j][c] = 0ull;

#pragma unroll 4
    for (int k = 0; k < 32; k++) {
        float4 a = *(const float4*)&At[k][lane * 4];
        ull w0 = Ws[k][cg * 3 + 0];
        ull w1 = Ws[k][cg * 3 + 1];
        ull w2 = Ws[k][cg * 3 + 2];
        ull ax = f2u(a.x, a.x), ay = f2u(a.y, a.y);
        ull az = f2u(a.z, a.z), aw = f2u(a.w, a.w);
        acc[0][0] = ffma2(ax, w0, acc[0][0]);
        acc[1][0] = ffma2(ay, w0, acc[1][0]);
        acc[2][0] = ffma2(az, w0, acc[2][0]);
        acc[3][0] = ffma2(aw, w0, acc[3][0]);
        acc[0][1] = ffma2(ax, w1, acc[0][1]);
        acc[1][1] = ffma2(ay, w1, acc[1][1]);
        acc[2][1] = ffma2(az, w1, acc[2][1]);
        acc[3][1] = ffma2(aw, w1, acc[3][1]);
        acc[0][2] = ffma2(ax, w2, acc[0][2]);
        acc[1][2] = ffma2(ay, w2, acc[1][2]);
        acc[2][2] = ffma2(az, w2, acc[2][2]);
        acc[3][2] = ffma2(aw, w2, acc[3][2]);
    }

    float2 b0 = ((const float2*)be)[cg * 3 + 0];
    float2 b1 = ((const float2*)be)[cg * 3 + 1];
    float2 b2 = ((const float2*)be)[cg * 3 + 2];

    int poss[4];
#pragma unroll
    for (int j = 0; j < 4; j++) poss[j] = g_pos[e0 + lane * 4 + j];

#pragma unroll
    for (int j = 0; j < 4; j++) {
        float2* row = (float2*)(g_m + (size_t)poss[j] * 48 + cg * 6);
        float2 p0 = u2f(acc[j][0]);
        p0.x = fmaxf(p0.x + b0.x, 0.0f);
        p0.y = fmaxf(p0.y + b0.y, 0.0f);
        float2 p1 = u2f(acc[j][1]);
        p1.x = fmaxf(p1.x + b1.x, 0.0f);
        p1.y = fmaxf(p1.y + b1.y, 0.0f);
        float2 p2 = u2f(acc[j][2]);
        p2.x = fmaxf(p2.x + b2.x, 0.0f);
        p2.y = fmaxf(p2.y + b2.y, 0.0f);
        row[0] = p0;
        row[1] = p1;
        row[2] = p2;
    }
}

// ---------------- launch 4: h[d] = [nfeat[d] | mean_i m[i]*nfeat[ps[i]]] ----------------
__global__ __launch_bounds__(256) void k_meanM(const float* __restrict__ nfeat) {
    const int lane = threadIdx.x & 31;
    const int d = blockIdx.x * 8 + (threadIdx.x >> 5);
    if (d >= N_NODES) return;
    const unsigned beg = g_off[d];
    const unsigned end = g_off[d + 1];
    const unsigned deg = end - beg;
    float a0 = 0.f, a1 = 0.f;
    unsigned i = beg;
    for (; i + 2 <= end; i += 2) {
        int s0 = g_ps[i], s1 = g_ps[i + 1];
        const float* r0 = g_m + (size_t)i * 48;
        const float* r1 = r0 + 48;
        float m00 = r0[lane], m10 = r1[lane];
        float n00 = nfeat[s0 * 48 + lane], n10 = nfeat[s1 * 48 + lane];
        a0 = fmaf(m00, n00, a0);
        a0 = fmaf(m10, n10, a0);
        if (lane < 16) {
            float m01 = r0[32 + lane], m11 = r1[32 + lane];
            float n01 = nfeat[s0 * 48 + 32 + lane], n11 = nfeat[s1 * 48 + 32 + lane];
            a1 = fmaf(m01, n01, a1);
            a1 = fmaf(m11, n11, a1);
        }
    }
    if (i < end) {
        int s0 = g_ps[i];
        const float* r0 = g_m + (size_t)i * 48;
        a0 = fmaf(r0[lane], nfeat[s0 * 48 + lane], a0);
        if (lane < 16) a1 = fmaf(r0[32 + lane], nfeat[s0 * 48 + 32 + lane], a1);
    }
    float iv = __fdividef(1.0f, fmaxf((float)deg, 1.0f));
    float* hrow = (float*)g_h + (size_t)d * 96;
    hrow[lane] = nfeat[d * 48 + lane];
    hrow[48 + lane] = a0 * iv;
    if (lane < 16) {
        hrow[32 + lane] = nfeat[d * 48 + 32 + lane];
        hrow[80 + lane] = a1 * iv;
    }
}

// ---------------- launch 5: hn1[d] = mean(h[src]) (96f, warp/node, unroll 4) ----------------
__global__ __launch_bounds__(256) void k_dstB() {
    const int lane = threadIdx.x & 31;
    const int d = blockIdx.x * 8 + (threadIdx.x >> 5);
    if (d >= N_NODES) return;
    const unsigned beg = g_off[d];
    const unsigned end = g_off[d + 1];
    const unsigned deg = end - beg;
    const float* hf = (const float*)g_h;
    float a0 = 0.f, a1 = 0.f, a2 = 0.f;
    unsigned i = beg;
    for (; i + 4 <= end; i += 4) {
        int s0 = g_ps[i], s1 = g_ps[i + 1], s2 = g_ps[i + 2], s3 = g_ps[i + 3];
        const float* r0 = hf + (size_t)s0 * 96;
        const float* r1 = hf + (size_t)s1 * 96;
        const float* r2 = hf + (size_t)s2 * 96;
        const float* r3 = hf + (size_t)s3 * 96;
        float x00 = r0[lane], x01 = r0[32 + lane], x02 = r0[64 + lane];
        float x10 = r1[lane], x11 = r1[32 + lane], x12 = r1[64 + lane];
        float x20 = r2[lane], x21 = r2[32 + lane], x22 = r2[64 + lane];
        float x30 = r3[lane], x31 = r3[32 + lane], x32 = r3[64 + lane];
        a0 += (x00 + x10) + (x20 + x30);
        a1 += (x01 + x11) + (x21 + x31);
        a2 += (x02 + x12) + (x22 + x32);
    }
    for (; i < end; i++) {
        const float* r0 = hf + (size_t)g_ps[i] * 96;
        a0 += r0[lane];
        a1 += r0[32 + lane];
        a2 += r0[64 + lane];
    }
    float iv = __fdividef(1.0f, fmaxf((float)deg, 1.0f));
    float* o = (float*)g_hn1 + (size_t)d * 96;
    o[lane] = a0 * iv;
    o[32 + lane] = a1 * iv;
    o[64 + lane] = a2 * iv;
}

// ---------------- launch 6: GEMM1 + fused y-projection ----------------
__global__ __launch_bounds__(128) void k_gemm1y(const float* __restrict__ b1) {
    __shared__ __align__(16) float As[32][192];
    __shared__ __align__(16) float Hs[32][128];
    const int tid = threadIdx.x;
    const int node0 = blockIdx.x * 32;
    for (int i = tid; i < 32 * 48; i += 128) {
        int n = i / 48, kq = i % 48;
        int node = node0 + n;
        float4 v = (kq < 24) ? g_h[node * 24 + kq] : g_hn1[node * 24 + (kq - 24)];
        ((float4*)As[n])[kq] = v;
    }
    __syncthreads();

    const int lane = tid & 31;
    const int nb = (tid >> 5) * 8;
    const int c0 = lane * 4;
    {
        ull acc[8][4];
#pragma unroll
        for (int n = 0; n < 8; n++)
#pragma unroll
            for (int j = 0; j < 4; j++) acc[n][j] = 0ull;

        for (int kq = 0; kq < 48; kq++) {
            const int kpA = 2 * kq, kpB = 2 * kq + 1;
            ulonglong2 wA0 = *(const ulonglong2*)&g_W1p[kpA * 128 + c0];
            ulonglong2 wA1 = *(const ulonglong2*)&g_W1p[kpA * 128 + c0 + 2];
            ulonglong2 wB0 = *(const ulonglong2*)&g_W1p[kpB * 128 + c0];
            ulonglong2 wB1 = *(const ulonglong2*)&g_W1p[kpB * 128 + c0 + 2];
#pragma unroll
            for (int n = 0; n < 8; n++) {
                ulonglong2 a = *(const ulonglong2*)&As[nb + n][4 * kq];
                acc[n][0] = ffma2(a.x, wA0.x, acc[n][0]);
                acc[n][1] = ffma2(a.x, wA0.y, acc[n][1]);
                acc[n][2] = ffma2(a.x, wA1.x, acc[n][2]);
                acc[n][3] = ffma2(a.x, wA1.y, acc[n][3]);
                acc[n][0] = ffma2(a.y, wB0.x, acc[n][0]);
                acc[n][1] = ffma2(a.y, wB0.y, acc[n][1]);
                acc[n][2] = ffma2(a.y, wB1.x, acc[n][2]);
                acc[n][3] = ffma2(a.y, wB1.y, acc[n][3]);
            }
        }

        float4 bb = *(const float4*)&b1[c0];
#pragma unroll
        for (int n = 0; n < 8; n++) {
            float2 p0 = u2f(acc[n][0]), p1 = u2f(acc[n][1]);
            float2 p2 = u2f(acc[n][2]), p3 = u2f(acc[n][3]);
            float4 r;
            r.x = fmaxf(p0.x + p0.y + bb.x, 0.0f);
            r.y = fmaxf(p1.x + p1.y + bb.y, 0.0f);
            r.z = fmaxf(p2.x + p2.y + bb.z, 0.0f);
            r.w = fmaxf(p3.x + p3.y + bb.w, 0.0f);
            g_h1[(node0 + nb + n) * 32 + lane] = r;
            ((float4*)Hs[nb + n])[lane] = r;
        }
    }
    __syncthreads();

    // y phase: 4 nodes per half-warp, 16 col-groups
    const int cg = lane & 15;
    const int c1 = cg * 4;
    const int nb2 = (tid >> 5) * 8 + (lane >> 4) * 4;
    ull acc[4][4];
#pragma unroll
    for (int n = 0; n < 4; n++)
#pragma unroll
        for (int j = 0; j < 4; j++) acc[n][j] = 0ull;

    for (int kq = 0; kq < 32; kq++) {
        const int kpA = 2 * kq, kpB = 2 * kq + 1;
        ulonglong2 wA0 = *(const ulonglong2*)&g_W2np[kpA * 64 + c1];
        ulonglong2 wA1 = *(const ulonglong2*)&g_W2np[kpA * 64 + c1 + 2];
        ulonglong2 wB0 = *(const ulonglong2*)&g_W2np[kpB * 64 + c1];
        ulonglong2 wB1 = *(const ulonglong2*)&g_W2np[kpB * 64 + c1 + 2];
#pragma unroll
        for (int n = 0; n < 4; n++) {
            ulonglong2 a = *(const ulonglong2*)&Hs[nb2 + n][4 * kq];
            acc[n][0] = ffma2(a.x, wA0.x, acc[n][0]);
            acc[n][1] = ffma2(a.x, wA0.y, acc[n][1]);
            acc[n][2] = ffma2(a.x, wA1.x, acc[n][2]);
            acc[n][3] = ffma2(a.x, wA1.y, acc[n][3]);
            acc[n][0] = ffma2(a.y, wB0.x, acc[n][0]);
            acc[n][1] = ffma2(a.y, wB0.y, acc[n][1]);
            acc[n][2] = ffma2(a.y, wB1.x, acc[n][2]);
            acc[n][3] = ffma2(a.y, wB1.y, acc[n][3]);
        }
    }
#pragma unroll
    for (int n = 0; n < 4; n++) {
        float2 p0 = u2f(acc[n][0]), p1 = u2f(acc[n][1]);
        float2 p2 = u2f(acc[n][2]), p3 = u2f(acc[n][3]);
        float4 r;
        r.x = p0.x + p0.y;
        r.y = p1.x + p1.y;
        r.z = p2.x + p2.y;
        r.w = p3.x + p3.y;
        g_y[(node0 + nb2 + n) * 16 + cg] = r;
    }
}

// ---------------- launch 7: hn2y[d] = mean(y[src]) (64f, warp/node, unroll 4) ----------------
__global__ __launch_bounds__(256) void k_dstC() {
    const int lane = threadIdx.x & 31;
    const int d = blockIdx.x * 8 + (threadIdx.x >> 5);
    if (d >= N_NODES) return;
    const unsigned beg = g_off[d];
    const unsigned end = g_off[d + 1];
    const unsigned deg = end - beg;
    const float* yf = (const float*)g_y;
    float a0 = 0.f, a1 = 0.f;
    unsigned i = beg;
    for (; i + 4 <= end; i += 4) {
        int s0 = g_ps[i], s1 = g_ps[i + 1], s2 = g_ps[i + 2], s3 = g_ps[i + 3];
        float2 x0 = *(const float2*)&yf[(size_t)s0 * 64 + 2 * lane];
        float2 x1 = *(const float2*)&yf[(size_t)s1 * 64 + 2 * lane];
        float2 x2 = *(const float2*)&yf[(size_t)s2 * 64 + 2 * lane];
        float2 x3 = *(const float2*)&yf[(size_t)s3 * 64 + 2 * lane];
        a0 += (x0.x + x1.x) + (x2.x + x3.x);
        a1 += (x0.y + x1.y) + (x2.y + x3.y);
    }
    for (; i < end; i++) {
        float2 x = *(const float2*)&yf[(size_t)g_ps[i] * 64 + 2 * lane];
        a0 += x.x;
        a1 += x.y;
    }
    float iv = __fdividef(1.0f, fmaxf((float)deg, 1.0f));
    float2* o = (float2*)((float*)g_hn2y + (size_t)d * 64);
    o[lane] = make_float2(a0 * iv, a1 * iv);
}

// ---------------- launch 8: out = h1@W2s + b2 + hn2y ----------------
__global__ __launch_bounds__(64) void k_gemm2s(const float* __restrict__ b2,
                                               float* __restrict__ out) {
    __shared__ __align__(16) float As[32][128];
    const int tid = threadIdx.x;
    const int node0 = blockIdx.x * 32;
    for (int i = tid; i < 32 * 32; i += 64) {
        int n = i / 32, kq = i % 32;
        ((float4*)As[n])[kq] = g_h1[(node0 + n) * 32 + kq];
    }
    __syncthreads();

    const int lane = tid & 31;
    const int cg = lane & 15;
    const int c0 = cg * 4;
    const int nb = (tid >> 5) * 16 + (lane >> 4) * 8;
    ull acc[8][4];
#pragma unroll
    for (int n = 0; n < 8; n++)
#pragma unroll
        for (int j = 0; j < 4; j++) acc[n][j] = 0ull;

    for (int kq = 0; kq < 32; kq++) {
        const int kpA = 2 * kq, kpB = 2 * kq + 1;
        ulonglong2 wA0 = *(const ulonglong2*)&g_W2sp[kpA * 64 + c0];
        ulonglong2 wA1 = *(const ulonglong2*)&g_W2sp[kpA * 64 + c0 + 2];
        ulonglong2 wB0 = *(const ulonglong2*)&g_W2sp[kpB * 64 + c0];
        ulonglong2 wB1 = *(const ulonglong2*)&g_W2sp[kpB * 64 + c0 + 2];
#pragma unroll
        for (int n = 0; n < 8; n++) {
            ulonglong2 a = *(const ulonglong2*)&As[nb + n][4 * kq];
            acc[n][0] = ffma2(a.x, wA0.x, acc[n][0]);
            acc[n][1] = ffma2(a.x, wA0.y, acc[n][1]);
            acc[n][2] = ffma2(a.x, wA1.x, acc[n][2]);
            acc[n][3] = ffma2(a.x, wA1.y, acc[n][3]);
            acc[n][0] = ffma2(a.y, wB0.x, acc[n][0]);
            acc[n][1] = ffma2(a.y, wB0.y, acc[n][1]);
            acc[n][2] = ffma2(a.y, wB1.x, acc[n][2]);
            acc[n][3] = ffma2(a.y, wB1.y, acc[n][3]);
        }
    }

    float4 bb = *(const float4*)&b2[c0];
    float4* out4 = (float4*)out;
#pragma unroll
    for (int n = 0; n < 8; n++) {
        int node = node0 + nb + n;
        float4 hz = g_hn2y[node * 16 + cg];
        float2 p0 = u2f(acc[n][0]), p1 = u2f(acc[n][1]);
        float2 p2 = u2f(acc[n][2]), p3 = u2f(acc[n][3]);
        float4 r;
        r.x = p0.x + p0.y + bb.x + hz.x;
        r.y = p1.x + p1.y + bb.y + hz.y;
        r.z = p2.x + p2.y + bb.z + hz.z;
        r.w = p3.x + p3.y + bb.w + hz.w;
        out4[node * 16 + cg] = r;
    }
}

// ---------------- launch ----------------
extern "C" void kernel_launch(void* const* d_in, const int* in_sizes, int n_in,
                              void* d_out, int out_size) {
    const float* nfeat = (const float*)d_in[0];
    const float* efeat = (const float*)d_in[1];
    const int*   src   = (const int*)d_in[2];
    const int*   dst   = (const int*)d_in[3];
    const float* We    = (const float*)d_in[4];
    const float* be    = (const float*)d_in[5];
    const float* W1s   = (const float*)d_in[6];
    const float* W1n   = (const float*)d_in[7];
    const float* b1    = (const float*)d_in[8];
    const float* W2s   = (const float*)d_in[9];
    const float* W2n   = (const float*)d_in[10];
    const float* b2    = (const float*)d_in[11];
    float* out = (float*)d_out;

    k_histprep<<<1184, 256>>>(dst, We, W1s, W1n, W2s, W2n);   // 0
    k_scan<<<SCAN_NB, 256>>>();                               // 1
    k_scatter<<<1184, 256>>>(src, dst);                       // 2
    k_edgeGEMM<<<N_EDGES / TILE_E, 256>>>(efeat, be);         // 3  <- profiled
    k_meanM<<<(N_NODES + 7) / 8, 256>>>(nfeat);               // 4
    k_dstB<<<(N_NODES + 7) / 8, 256>>>();                     // 5
    k_gemm1y<<<N_NODES / 32, 128>>>(b1);                      // 6
    k_dstC<<<(N_NODES + 7) / 8, 256>>>();                     // 7
    k_gemm2s<<<N_NODES / 32, 64>>>(b2, out);                  // 8
}

// round 8
// speedup vs baseline: 1.4606x; 1.1787x over previous
#include <cuda_runtime.h>
#include <cstdint>

#define N_NODES 100000
#define N_EDGES 1600000
#define IN_F   48
#define EDGE_F 32
#define HID_F  128
#define OUT_F  64

typedef unsigned long long ull;

#define SCAN_NB 391   // ceil(N_NODES/256)
#define TILE_E 128

// ---------------- scratch (device globals; allocation-free, .bss zero) ----------------
__device__ float4 g_h[N_NODES * 24];     // [N,96]  = [nfeat | mean-neigh0]
__device__ float4 g_hn1[N_NODES * 24];   // [N,96]  mean of h[src] per dst
__device__ float4 g_h1[N_NODES * 32];    // [N,128]
__device__ float4 g_y[N_NODES * 16];     // [N,64]  = h1 @ W2n
__device__ float4 g_hn2y[N_NODES * 16];  // [N,64]  mean of y[src] per dst
__device__ float  g_m[(size_t)N_EDGES * 48];  // per-edge relu(e), EDGE order
__device__ unsigned g_cnt[N_NODES];      // in-degree (re-zeroed each run)
__device__ unsigned g_off[N_NODES + 1];  // CSR offsets
__device__ unsigned g_cur[N_NODES];      // scatter cursors
__device__ unsigned g_stat[512];         // lookback status (re-zeroed each run)
__device__ int g_ps[N_EDGES];            // src grouped by dst (CSR order)
__device__ int g_pe[N_EDGES];            // edge id grouped by dst (CSR order)

// packed weights
__device__ ull g_Wecp[32 * 24];          // We col-pair packed: [k][cp]=(W[k][2cp],W[k][2cp+1])
__device__ ull g_W1p[96 * 128];          // [W1s;W1n] k-pair packed
__device__ ull g_W2sp[64 * 64];          // W2s k-pair packed
__device__ ull g_W2np[64 * 64];          // W2n k-pair packed

// ---------------- helpers ----------------
__device__ __forceinline__ ull ffma2(ull a, ull b, ull c) {
    ull d;
    asm("fma.rn.f32x2 %0, %1, %2, %3;" : "=l"(d) : "l"(a), "l"(b), "l"(c));
    return d;
}
__device__ __forceinline__ ull f2u(float x, float y) {
    ull r;
    asm("mov.b64 %0, {%1,%2};" : "=l"(r) : "f"(x), "f"(y));
    return r;
}
__device__ __forceinline__ float2 u2f(ull v) {
    float2 r;
    asm("mov.b64 {%0,%1}, %2;" : "=f"(r.x), "=f"(r.y) : "l"(v));
    return r;
}
__device__ __forceinline__ void red_u32(unsigned* p, unsigned v) {
    asm volatile("red.global.add.u32 [%0], %1;" :: "l"(p), "r"(v) : "memory");
}

// ---------------- launch 0: weight prepack + degree histogram ----------------
__global__ void k_histprep(const int* __restrict__ dst, const float* __restrict__ We,
                           const float* __restrict__ W1s, const float* __restrict__ W1n,
                           const float* __restrict__ W2s, const float* __restrict__ W2n) {
    const int T0 = 32 * 24;
    const int T1 = T0 + 96 * 128;
    const int T2 = T1 + 64 * 64;
    const int T3 = T2 + 64 * 64;
    const int tid = blockIdx.x * blockDim.x + threadIdx.x;
    const int stride = gridDim.x * blockDim.x;
    for (int i = tid; i < T3; i += stride) {
        if (i < T0) {
            int k = i / 24, cp = i % 24;
            g_Wecp[i] = f2u(We[k * 48 + 2 * cp], We[k * 48 + 2 * cp + 1]);
        } else if (i < T1) {
            int j = i - T0, kp = j / 128, c = j % 128;
            const float* W = (kp < 48) ? W1s : W1n;
            int k0 = (kp < 48) ? 2 * kp : 2 * (kp - 48);
            g_W1p[j] = f2u(W[k0 * 128 + c], W[(k0 + 1) * 128 + c]);
        } else if (i < T2) {
            int j = i - T1, kp = j / 64, c = j % 64;
            g_W2sp[j] = f2u(W2s[(2 * kp) * 64 + c], W2s[(2 * kp + 1) * 64 + c]);
        } else {
            int j = i - T2, kp = j / 64, c = j % 64;
            g_W2np[j] = f2u(W2n[(2 * kp) * 64 + c], W2n[(2 * kp + 1) * 64 + c]);
        }
    }
    for (int e = tid; e < N_EDGES; e += stride) red_u32(&g_cnt[dst[e]], 1u);
}

// ---------------- launch 1: single-kernel exclusive scan (decoupled lookback) ----------------
__global__ __launch_bounds__(256) void k_scan() {
    __shared__ unsigned sh[256];
    __shared__ unsigned s_excl;
    const int b = blockIdx.x, t = threadIdx.x;
    const int i = b * 256 + t;
    unsigned v = (i < N_NODES) ? g_cnt[i] : 0u;
    sh[t] = v;
    __syncthreads();
#pragma unroll
    for (int ofs = 1; ofs < 256; ofs <<= 1) {
        unsigned x = (t >= ofs) ? sh[t - ofs] : 0u;
        __syncthreads();
        sh[t] += x;
        __syncthreads();
    }
    const unsigned incl = sh[t];
    const unsigned T = sh[255];
    if (t == 0) {
        if (b > 0) atomicExch(&g_stat[b], 0x40000000u | T);  // AGG
        unsigned excl = 0;
        if (b > 0) {
            int p = b - 1;
            while (true) {
                unsigned s;
                do { s = *(volatile unsigned*)&g_stat[p]; } while (s < 0x40000000u);
                excl += s & 0x3FFFFFFFu;
                if (s >= 0x80000000u) break;  // PREFIX
                p--;
            }
        }
        atomicExch(&g_stat[b], 0x80000000u | (excl + T));
        s_excl = excl;
    }
    __syncthreads();
    if (i < N_NODES) {
        unsigned o = s_excl + incl - v;
        g_off[i] = o;
        g_cur[i] = o;
        g_cnt[i] = 0u;  // re-zero for next launch
    }
    if (i == 0) g_off[N_NODES] = N_EDGES;
}

// ---------------- launch 2: scatter (build g_ps + g_pe in CSR order) ----------------
__global__ void k_scatter(const int* __restrict__ src, const int* __restrict__ dst) {
    const int tid = blockIdx.x * blockDim.x + threadIdx.x;
    if (tid < 512) g_stat[tid] = 0u;
    const int stride = gridDim.x * blockDim.x;
    for (int e = tid; e < N_EDGES; e += stride) {
        int d = dst[e];
        unsigned pos = atomicAdd(&g_cur[d], 1u);
        g_ps[pos] = src[e];
        g_pe[pos] = e;
    }
}

// ---------------- launch 3: tiled GEMM: g_m[e] = relu(efeat[e]@We + be), edge order ----------------
// block 256 thr; tile 128 edges x 48 cols; warp <-> 6-col group; lane <-> 4 edges.
#define MSTRIDE 49
__global__ __launch_bounds__(256) void k_edgeGEMM(const float* __restrict__ efeat,
                                                  const float* __restrict__ be) {
    __shared__ __align__(16) float sbuf[TILE_E * MSTRIDE];  // phase1: At[32][132]; phase2: Mout[128][49]
    __shared__ ull Ws[32][24];                              // col-pair-packed We
    float (*At)[132] = (float(*)[132])sbuf;
    const int tid = threadIdx.x;
    const int e0 = blockIdx.x * TILE_E;

    for (int i = tid; i < 32 * 24; i += 256) ((ull*)Ws)[i] = g_Wecp[i];

    // load + transpose efeat tile (coalesced float4 reads, scalar STS)
    const float4* ef4 = (const float4*)efeat + (size_t)e0 * 8;
#pragma unroll
    for (int i = 0; i < 4; i++) {
        int idx = tid + 256 * i;
        int e = idx >> 3, q = idx & 7;
        float4 v = ef4[e * 8 + q];
        At[4 * q + 0][e] = v.x;
        At[4 * q + 1][e] = v.y;
        At[4 * q + 2][e] = v.z;
        At[4 * q + 3][e] = v.w;
    }
    __syncthreads();

    const int lane = tid & 31;
    const int cg = tid >> 5;  // 0..7
    ull acc[4][3];
#pragma unroll
    for (int j = 0; j < 4; j++)
#pragma unroll
        for (int c = 0; c < 3; c++) acc[j][c] = 0ull;

#pragma unroll 4
    for (int k = 0; k < 32; k++) {
        float4 a = *(const float4*)&At[k][lane * 4];
        ull w0 = Ws[k][cg * 3 + 0];
        ull w1 = Ws[k][cg * 3 + 1];
        ull w2 = Ws[k][cg * 3 + 2];
        ull ax = f2u(a.x, a.x), ay = f2u(a.y, a.y);
        ull az = f2u(a.z, a.z), aw = f2u(a.w, a.w);
        acc[0][0] = ffma2(ax, w0, acc[0][0]);
        acc[1][0] = ffma2(ay, w0, acc[1][0]);
        acc[2][0] = ffma2(az, w0, acc[2][0]);
        acc[3][0] = ffma2(aw, w0, acc[3][0]);
        acc[0][1] = ffma2(ax, w1, acc[0][1]);
        acc[1][1] = ffma2(ay, w1, acc[1][1]);
        acc[2][1] = ffma2(az, w1, acc[2][1]);
        acc[3][1] = ffma2(aw, w1, acc[3][1]);
        acc[0][2] = ffma2(ax, w2, acc[0][2]);
        acc[1][2] = ffma2(ay, w2, acc[1][2]);
        acc[2][2] = ffma2(az, w2, acc[2][2]);
        acc[3][2] = ffma2(aw, w2, acc[3][2]);
    }

    float2 b0 = ((const float2*)be)[cg * 3 + 0];
    float2 b1 = ((const float2*)be)[cg * 3 + 1];
    float2 b2 = ((const float2*)be)[cg * 3 + 2];

    __syncthreads();  // all At reads done before aliasing as Mout

    // bias + relu, stage into Mout (row stride 49 floats, odd -> bounded conflicts)
#pragma unroll
    for (int j = 0; j < 4; j++) {
        float* row = sbuf + (lane * 4 + j) * MSTRIDE + cg * 6;
        float2 p0 = u2f(acc[j][0]);
        row[0] = fmaxf(p0.x + b0.x, 0.0f);
        row[1] = fmaxf(p0.y + b0.y, 0.0f);
        float2 p1 = u2f(acc[j][1]);
        row[2] = fmaxf(p1.x + b1.x, 0.0f);
        row[3] = fmaxf(p1.y + b1.y, 0.0f);
        float2 p2 = u2f(acc[j][2]);
        row[4] = fmaxf(p2.x + b2.x, 0.0f);
        row[5] = fmaxf(p2.y + b2.y, 0.0f);
    }
    __syncthreads();

    // coalesced contiguous write-out: tile occupies g_m[e0*48 .. e0*48+6144)
    float* gout = g_m + (size_t)e0 * 48;
#pragma unroll
    for (int r = 0; r < 24; r++) {
        int i = r * 256 + tid;
        int e = i / 48, c = i - e * 48;
        gout[i] = sbuf[e * MSTRIDE + c];
    }
}

// ---------------- launch 4: h[d] = [nfeat[d] | mean_i m[pe[i]]*nfeat[ps[i]]] ----------------
__global__ __launch_bounds__(256) void k_meanM(const float* __restrict__ nfeat) {
    const int lane = threadIdx.x & 31;
    const int d = blockIdx.x * 8 + (threadIdx.x >> 5);
    if (d >= N_NODES) return;
    const unsigned beg = g_off[d];
    const unsigned end = g_off[d + 1];
    const unsigned deg = end - beg;
    float a0 = 0.f, a1 = 0.f;
    unsigned i = beg;
    for (; i + 4 <= end; i += 4) {
        int s0 = g_ps[i], s1 = g_ps[i + 1], s2 = g_ps[i + 2], s3 = g_ps[i + 3];
        int e0 = g_pe[i], e1 = g_pe[i + 1], e2 = g_pe[i + 2], e3 = g_pe[i + 3];
        const float* r0 = g_m + (size_t)e0 * 48;
        const float* r1 = g_m + (size_t)e1 * 48;
        const float* r2 = g_m + (size_t)e2 * 48;
        const float* r3 = g_m + (size_t)e3 * 48;
        float m0 = r0[lane], m1 = r1[lane], m2 = r2[lane], m3 = r3[lane];
        float n0 = nfeat[s0 * 48 + lane], n1 = nfeat[s1 * 48 + lane];
        float n2 = nfeat[s2 * 48 + lane], n3 = nfeat[s3 * 48 + lane];
        a0 = fmaf(m0, n0, a0);
        a0 = fmaf(m1, n1, a0);
        a0 = fmaf(m2, n2, a0);
        a0 = fmaf(m3, n3, a0);
        if (lane < 16) {
            float q0 = r0[32 + lane], q1 = r1[32 + lane];
            float q2 = r2[32 + lane], q3 = r3[32 + lane];
            float u0 = nfeat[s0 * 48 + 32 + lane], u1 = nfeat[s1 * 48 + 32 + lane];
            float u2 = nfeat[s2 * 48 + 32 + lane], u3 = nfeat[s3 * 48 + 32 + lane];
            a1 = fmaf(q0, u0, a1);
            a1 = fmaf(q1, u1, a1);
            a1 = fmaf(q2, u2, a1);
            a1 = fmaf(q3, u3, a1);
        }
    }
    for (; i < end; i++) {
        int s0 = g_ps[i], e0 = g_pe[i];
        const float* r0 = g_m + (size_t)e0 * 48;
        a0 = fmaf(r0[lane], nfeat[s0 * 48 + lane], a0);
        if (lane < 16) a1 = fmaf(r0[32 + lane], nfeat[s0 * 48 + 32 + lane], a1);
    }
    float iv = __fdividef(1.0f, fmaxf((float)deg, 1.0f));
    float* hrow = (float*)g_h + (size_t)d * 96;
    hrow[lane] = nfeat[d * 48 + lane];
    hrow[48 + lane] = a0 * iv;
    if (lane < 16) {
        hrow[32 + lane] = nfeat[d * 48 + 32 + lane];
        hrow[80 + lane] = a1 * iv;
    }
}

// ---------------- launch 5: hn1[d] = mean(h[src]) (96f, warp/node, unroll 4) ----------------
__global__ __launch_bounds__(256) void k_dstB() {
    const int lane = threadIdx.x & 31;
    const int d = blockIdx.x * 8 + (threadIdx.x >> 5);
    if (d >= N_NODES) return;
    const unsigned beg = g_off[d];
    const unsigned end = g_off[d + 1];
    const unsigned deg = end - beg;
    const float* hf = (const float*)g_h;
    float a0 = 0.f, a1 = 0.f, a2 = 0.f;
    unsigned i = beg;
    for (; i + 4 <= end; i += 4) {
        int s0 = g_ps[i], s1 = g_ps[i + 1], s2 = g_ps[i + 2], s3 = g_ps[i + 3];
        const float* r0 = hf + (size_t)s0 * 96;
        const float* r1 = hf + (size_t)s1 * 96;
        const float* r2 = hf + (size_t)s2 * 96;
        const float* r3 = hf + (size_t)s3 * 96;
        float x00 = r0[lane], x01 = r0[32 + lane], x02 = r0[64 + lane];
        float x10 = r1[lane], x11 = r1[32 + lane], x12 = r1[64 + lane];
        float x20 = r2[lane], x21 = r2[32 + lane], x22 = r2[64 + lane];
        float x30 = r3[lane], x31 = r3[32 + lane], x32 = r3[64 + lane];
        a0 += (x00 + x10) + (x20 + x30);
        a1 += (x01 + x11) + (x21 + x31);
        a2 += (x02 + x12) + (x22 + x32);
    }
    for (; i < end; i++) {
        const float* r0 = hf + (size_t)g_ps[i] * 96;
        a0 += r0[lane];
        a1 += r0[32 + lane];
        a2 += r0[64 + lane];
    }
    float iv = __fdividef(1.0f, fmaxf((float)deg, 1.0f));
    float* o = (float*)g_hn1 + (size_t)d * 96;
    o[lane] = a0 * iv;
    o[32 + lane] = a1 * iv;
    o[64 + lane] = a2 * iv;
}

// ---------------- launch 6: GEMM1 + fused y-projection ----------------
__global__ __launch_bounds__(128) void k_gemm1y(const float* __restrict__ b1) {
    __shared__ __align__(16) float As[32][192];
    __shared__ __align__(16) float Hs[32][128];
    const int tid = threadIdx.x;
    const int node0 = blockIdx.x * 32;
    for (int i = tid; i < 32 * 48; i += 128) {
        int n = i / 48, kq = i % 48;
        int node = node0 + n;
        float4 v = (kq < 24) ? g_h[node * 24 + kq] : g_hn1[node * 24 + (kq - 24)];
        ((float4*)As[n])[kq] = v;
    }
    __syncthreads();

    const int lane = tid & 31;
    const int nb = (tid >> 5) * 8;
    const int c0 = lane * 4;
    {
        ull acc[8][4];
#pragma unroll
        for (int n = 0; n < 8; n++)
#pragma unroll
            for (int j = 0; j < 4; j++) acc[n][j] = 0ull;

        for (int kq = 0; kq < 48; kq++) {
            const int kpA = 2 * kq, kpB = 2 * kq + 1;
            ulonglong2 wA0 = *(const ulonglong2*)&g_W1p[kpA * 128 + c0];
            ulonglong2 wA1 = *(const ulonglong2*)&g_W1p[kpA * 128 + c0 + 2];
            ulonglong2 wB0 = *(const ulonglong2*)&g_W1p[kpB * 128 + c0];
            ulonglong2 wB1 = *(const ulonglong2*)&g_W1p[kpB * 128 + c0 + 2];
#pragma unroll
            for (int n = 0; n < 8; n++) {
                ulonglong2 a = *(const ulonglong2*)&As[nb + n][4 * kq];
                acc[n][0] = ffma2(a.x, wA0.x, acc[n][0]);
                acc[n][1] = ffma2(a.x, wA0.y, acc[n][1]);
                acc[n][2] = ffma2(a.x, wA1.x, acc[n][2]);
                acc[n][3] = ffma2(a.x, wA1.y, acc[n][3]);
                acc[n][0] = ffma2(a.y, wB0.x, acc[n][0]);
                acc[n][1] = ffma2(a.y, wB0.y, acc[n][1]);
                acc[n][2] = ffma2(a.y, wB1.x, acc[n][2]);
                acc[n][3] = ffma2(a.y, wB1.y, acc[n][3]);
            }
        }

        float4 bb = *(const float4*)&b1[c0];
#pragma unroll
        for (int n = 0; n < 8; n++) {
            float2 p0 = u2f(acc[n][0]), p1 = u2f(acc[n][1]);
            float2 p2 = u2f(acc[n][2]), p3 = u2f(acc[n][3]);
            float4 r;
            r.x = fmaxf(p0.x + p0.y + bb.x, 0.0f);
            r.y = fmaxf(p1.x + p1.y + bb.y, 0.0f);
            r.z = fmaxf(p2.x + p2.y + bb.z, 0.0f);
            r.w = fmaxf(p3.x + p3.y + bb.w, 0.0f);
            g_h1[(node0 + nb + n) * 32 + lane] = r;
            ((float4*)Hs[nb + n])[lane] = r;
        }
    }
    __syncthreads();

    // y phase: 4 nodes per half-warp, 16 col-groups
    const int cg = lane & 15;
    const int c1 = cg * 4;
    const int nb2 = (tid >> 5) * 8 + (lane >> 4) * 4;
    ull acc[4][4];
#pragma unroll
    for (int n = 0; n < 4; n++)
#pragma unroll
        for (int j = 0; j < 4; j++) acc[n][j] = 0ull;

    for (int kq = 0; kq < 32; kq++) {
        const int kpA = 2 * kq, kpB = 2 * kq + 1;
        ulonglong2 wA0 = *(const ulonglong2*)&g_W2np[kpA * 64 + c1];
        ulonglong2 wA1 = *(const ulonglong2*)&g_W2np[kpA * 64 + c1 + 2];
        ulonglong2 wB0 = *(const ulonglong2*)&g_W2np[kpB * 64 + c1];
        ulonglong2 wB1 = *(const ulonglong2*)&g_W2np[kpB * 64 + c1 + 2];
#pragma unroll
        for (int n = 0; n < 4; n++) {
            ulonglong2 a = *(const ulonglong2*)&Hs[nb2 + n][4 * kq];
            acc[n][0] = ffma2(a.x, wA0.x, acc[n][0]);
            acc[n][1] = ffma2(a.x, wA0.y, acc[n][1]);
            acc[n][2] = ffma2(a.x, wA1.x, acc[n][2]);
            acc[n][3] = ffma2(a.x, wA1.y, acc[n][3]);
            acc[n][0] = ffma2(a.y, wB0.x, acc[n][0]);
            acc[n][1] = ffma2(a.y, wB0.y, acc[n][1]);
            acc[n][2] = ffma2(a.y, wB1.x, acc[n][2]);
            acc[n][3] = ffma2(a.y, wB1.y, acc[n][3]);
        }
    }
#pragma unroll
    for (int n = 0; n < 4; n++) {
        float2 p0 = u2f(acc[n][0]), p1 = u2f(acc[n][1]);
        float2 p2 = u2f(acc[n][2]), p3 = u2f(acc[n][3]);
        float4 r;
        r.x = p0.x + p0.y;
        r.y = p1.x + p1.y;
        r.z = p2.x + p2.y;
        r.w = p3.x + p3.y;
        g_y[(node0 + nb2 + n) * 16 + cg] = r;
    }
}

// ---------------- launch 7: hn2y[d] = mean(y[src]) (64f, warp/node, unroll 4) ----------------
__global__ __launch_bounds__(256) void k_dstC() {
    const int lane = threadIdx.x & 31;
    const int d = blockIdx.x * 8 + (threadIdx.x >> 5);
    if (d >= N_NODES) return;
    const unsigned beg = g_off[d];
    const unsigned end = g_off[d + 1];
    const unsigned deg = end - beg;
    const float* yf = (const float*)g_y;
    float a0 = 0.f, a1 = 0.f;
    unsigned i = beg;
    for (; i + 4 <= end; i += 4) {
        int s0 = g_ps[i], s1 = g_ps[i + 1], s2 = g_ps[i + 2], s3 = g_ps[i + 3];
        float2 x0 = *(const float2*)&yf[(size_t)s0 * 64 + 2 * lane];
        float2 x1 = *(const float2*)&yf[(size_t)s1 * 64 + 2 * lane];
        float2 x2 = *(const float2*)&yf[(size_t)s2 * 64 + 2 * lane];
        float2 x3 = *(const float2*)&yf[(size_t)s3 * 64 + 2 * lane];
        a0 += (x0.x + x1.x) + (x2.x + x3.x);
        a1 += (x0.y + x1.y) + (x2.y + x3.y);
    }
    for (; i < end; i++) {
        float2 x = *(const float2*)&yf[(size_t)g_ps[i] * 64 + 2 * lane];
        a0 += x.x;
        a1 += x.y;
    }
    float iv = __fdividef(1.0f, fmaxf((float)deg, 1.0f));
    float2* o = (float2*)((float*)g_hn2y + (size_t)d * 64);
    o[lane] = make_float2(a0 * iv, a1 * iv);
}

// ---------------- launch 8: out = h1@W2s + b2 + hn2y ----------------
__global__ __launch_bounds__(64) void k_gemm2s(const float* __restrict__ b2,
                                               float* __restrict__ out) {
    __shared__ __align__(16) float As[32][128];
    const int tid = threadIdx.x;
    const int node0 = blockIdx.x * 32;
    for (int i = tid; i < 32 * 32; i += 64) {
        int n = i / 32, kq = i % 32;
        ((float4*)As[n])[kq] = g_h1[(node0 + n) * 32 + kq];
    }
    __syncthreads();

    const int lane = tid & 31;
    const int cg = lane & 15;
    const int c0 = cg * 4;
    const int nb = (tid >> 5) * 16 + (lane >> 4) * 8;
    ull acc[8][4];
#pragma unroll
    for (int n = 0; n < 8; n++)
#pragma unroll
        for (int j = 0; j < 4; j++) acc[n][j] = 0ull;

    for (int kq = 0; kq < 32; kq++) {
        const int kpA = 2 * kq, kpB = 2 * kq + 1;
        ulonglong2 wA0 = *(const ulonglong2*)&g_W2sp[kpA * 64 + c0];
        ulonglong2 wA1 = *(const ulonglong2*)&g_W2sp[kpA * 64 + c0 + 2];
        ulonglong2 wB0 = *(const ulonglong2*)&g_W2sp[kpB * 64 + c0];
        ulonglong2 wB1 = *(const ulonglong2*)&g_W2sp[kpB * 64 + c0 + 2];
#pragma unroll
        for (int n = 0; n < 8; n++) {
            ulonglong2 a = *(const ulonglong2*)&As[nb + n][4 * kq];
            acc[n][0] = ffma2(a.x, wA0.x, acc[n][0]);
            acc[n][1] = ffma2(a.x, wA0.y, acc[n][1]);
            acc[n][2] = ffma2(a.x, wA1.x, acc[n][2]);
            acc[n][3] = ffma2(a.x, wA1.y, acc[n][3]);
            acc[n][0] = ffma2(a.y, wB0.x, acc[n][0]);
            acc[n][1] = ffma2(a.y, wB0.y, acc[n][1]);
            acc[n][2] = ffma2(a.y, wB1.x, acc[n][2]);
            acc[n][3] = ffma2(a.y, wB1.y, acc[n][3]);
        }
    }

    float4 bb = *(const float4*)&b2[c0];
    float4* out4 = (float4*)out;
#pragma unroll
    for (int n = 0; n < 8; n++) {
        int node = node0 + nb + n;
        float4 hz = g_hn2y[node * 16 + cg];
        float2 p0 = u2f(acc[n][0]), p1 = u2f(acc[n][1]);
        float2 p2 = u2f(acc[n][2]), p3 = u2f(acc[n][3]);
        float4 r;
        r.x = p0.x + p0.y + bb.x + hz.x;
        r.y = p1.x + p1.y + bb.y + hz.y;
        r.z = p2.x + p2.y + bb.z + hz.z;
        r.w = p3.x + p3.y + bb.w + hz.w;
        out4[node * 16 + cg] = r;
    }
}

// ---------------- launch ----------------
extern "C" void kernel_launch(void* const* d_in, const int* in_sizes, int n_in,
                              void* d_out, int out_size) {
    const float* nfeat = (const float*)d_in[0];
    const float* efeat = (const float*)d_in[1];
    const int*   src   = (const int*)d_in[2];
    const int*   dst   = (const int*)d_in[3];
    const float* We    = (const float*)d_in[4];
    const float* be    = (const float*)d_in[5];
    const float* W1s   = (const float*)d_in[6];
    const float* W1n   = (const float*)d_in[7];
    const float* b1    = (const float*)d_in[8];
    const float* W2s   = (const float*)d_in[9];
    const float* W2n   = (const float*)d_in[10];
    const float* b2    = (const float*)d_in[11];
    float* out = (float*)d_out;

    k_histprep<<<1184, 256>>>(dst, We, W1s, W1n, W2s, W2n);   // 0
    k_scan<<<SCAN_NB, 256>>>();                               // 1
    k_scatter<<<1184, 256>>>(src, dst);                       // 2
    k_edgeGEMM<<<N_EDGES / TILE_E, 256>>>(efeat, be);         // 3  <- profiled
    k_meanM<<<(N_NODES + 7) / 8, 256>>>(nfeat);               // 4
    k_dstB<<<(N_NODES + 7) / 8, 256>>>();                     // 5
    k_gemm1y<<<N_NODES / 32, 128>>>(b1);                      // 6
    k_dstC<<<(N_NODES + 7) / 8, 256>>>();                     // 7
    k_gemm2s<<<N_NODES / 32, 64>>>(b2, out);                  // 8
}